// round 5
// baseline (speedup 1.0000x reference)
#include <cuda_runtime.h>

#define BB 512
#define NN 90
#define DD 1024
#define KK 45
#define THREADS 512
#define WARPS 16
#define QUARTERS 4
#define TOTAL_TASKS (BB * QUARTERS)

// Device-global scratch (no allocation allowed)
__device__ unsigned g_task_counter;
__device__ unsigned g_done;
__device__ unsigned g_arrive[BB];
__device__ float    g_scores[BB][NN];

__global__ __launch_bounds__(THREADS, 2)
void multig_pool_kernel(const float* __restrict__ x_sc,
                        const float* __restrict__ x_fc,
                        const float* __restrict__ pool_w,
                        const float* __restrict__ multi_w,
                        const float* __restrict__ multi_b,
                        float* __restrict__ out)
{
    __shared__ __align__(16) float spw[DD];
    __shared__ float s_scores[NN];
    __shared__ int   sel_idx[KK];
    __shared__ float sel_w[KK];
    __shared__ float red[WARPS];
    __shared__ float s_invnorm;
    __shared__ unsigned s_task;
    __shared__ unsigned s_last;

    const int tid  = threadIdx.x;
    const int wid  = tid >> 5;
    const int lane = tid & 31;

    // ---- Once per CTA: stage pool_w, compute 1/||pool_w|| ----
    float pw2 = 0.f;
    {
        float v0 = pool_w[tid];
        float v1 = pool_w[tid + THREADS];
        spw[tid]           = v0;
        spw[tid + THREADS] = v1;
        pw2 = v0 * v0 + v1 * v1;
    }
    #pragma unroll
    for (int off = 16; off; off >>= 1) pw2 += __shfl_xor_sync(0xffffffffu, pw2, off);
    if (lane == 0) red[wid] = pw2;
    __syncthreads();
    if (tid == 0) {
        float s = 0.f;
        #pragma unroll
        for (int i = 0; i < WARPS; i++) s += red[i];
        s_invnorm = rsqrtf(s);
    }
    __syncthreads();

    const float inv_norm = s_invnorm;
    const float mw0 = multi_w[0];
    const float mw1 = multi_w[1];
    const float4* __restrict__ pw4 = (const float4*)spw;

    // ---- Persistent work loop: task = (batch, quarter) ----
    for (;;) {
        if (tid == 0) s_task = atomicAdd(&g_task_counter, 1u);
        __syncthreads();
        const unsigned task = s_task;
        if (task >= TOTAL_TASKS) break;

        const int b = (int)(task >> 2);
        const int q = (int)(task & 3);

        const float* __restrict__ xb_sc = x_sc + (size_t)b * NN * DD;
        const float* __restrict__ xb_fc = x_fc + (size_t)b * NN * DD;

        // ===== Score this quarter's nodes: n = q + 4*j =====
        const int cnt = (NN - q + 3) >> 2;   // 23,23,22,22
        for (int j = wid; j < cnt; j += WARPS) {
            const int n = q + 4 * j;
            const float4* rs = (const float4*)(xb_sc + (size_t)n * DD);
            const float4* rf = (const float4*)(xb_fc + (size_t)n * DD);
            float dsc = 0.f, dfc = 0.f;
            #pragma unroll
            for (int i = 0; i < 8; i++) {
                int jj = lane + i * 32;
                float4 a = rs[jj];
                float4 c = rf[jj];
                float4 p = pw4[jj];
                dsc += a.x * p.x + a.y * p.y + a.z * p.z + a.w * p.w;
                dfc += c.x * p.x + c.y * p.y + c.z * p.z + c.w * p.w;
            }
            #pragma unroll
            for (int off = 16; off; off >>= 1) {
                dsc += __shfl_xor_sync(0xffffffffu, dsc, off);
                dfc += __shfl_xor_sync(0xffffffffu, dfc, off);
            }
            if (lane == 0) {
                float t0 = tanhf(dsc * inv_norm);
                float t1 = tanhf(dfc * inv_norm);
                float z  = t0 * mw0 + t1 * mw1 + multi_b[n];
                g_scores[b][n] = 1.f / (1.f + expf(-z));
            }
        }
        __syncthreads();

        // ===== Arrive + wait for the other 3 quarters =====
        if (tid == 0) {
            __threadfence();
            atomicAdd(&g_arrive[b], 1u);
            while (atomicAdd(&g_arrive[b], 0u) < QUARTERS) { }
        }
        __syncthreads();
        __threadfence();

        // ===== Selection (each quarter-CTA redundantly, cheap) =====
        if (tid < NN) s_scores[tid] = g_scores[b][tid];
        __syncthreads();
        if (tid < NN) {
            float my = s_scores[tid];
            int rank = 0;
            #pragma unroll 10
            for (int j = 0; j < NN; j++) {
                float sj = s_scores[j];
                rank += (sj > my) || (sj == my && j < tid);
            }
            if (rank < KK) { sel_idx[rank] = tid; sel_w[rank] = my; }
        }
        __syncthreads();

        // ===== Gather this quarter's share of the 90 output rows =====
        // Rows should still be L2-resident (read ~10us ago, 54MB in-flight set).
        float* __restrict__ out_sc = out + (size_t)b * KK * DD;
        float* __restrict__ out_fc = out + (size_t)BB * KK * DD + (size_t)b * KK * DD;

        const int cnt2 = (2 * KK - q + 3) >> 2;
        for (int m = wid; m < cnt2; m += WARPS) {
            const int r = q + 4 * m;         // 0..89
            const bool is_sc = (r < KK);
            const int  k = is_sc ? r : r - KK;
            const int  n = sel_idx[k];
            const float w = sel_w[k];
            const float4* src = (const float4*)((is_sc ? xb_sc : xb_fc) + (size_t)n * DD);
            float4* dst = (float4*)((is_sc ? out_sc : out_fc) + (size_t)k * DD);
            #pragma unroll
            for (int i = 0; i < 8; i++) {
                int jj = lane + i * 32;
                float4 v = src[jj];
                v.x *= w; v.y *= w; v.z *= w; v.w *= w;
                dst[jj] = v;
            }
        }
        __syncthreads();   // protect s_task/s_scores/sel reuse
    }

    // ---- Last CTA out resets device state for the next graph replay ----
    __syncthreads();
    if (tid == 0) {
        unsigned d = atomicAdd(&g_done, 1u);
        s_last = (d == gridDim.x - 1) ? 1u : 0u;
    }
    __syncthreads();
    if (s_last) {
        if (tid == 0) { g_task_counter = 0; g_done = 0; }
        for (int i = tid; i < BB; i += THREADS) g_arrive[i] = 0;
    }
}

extern "C" void kernel_launch(void* const* d_in, const int* in_sizes, int n_in,
                              void* d_out, int out_size)
{
    const float* x_sc    = (const float*)d_in[0];
    const float* x_fc    = (const float*)d_in[1];
    const float* pool_w  = (const float*)d_in[2];
    const float* multi_w = (const float*)d_in[3];
    const float* multi_b = (const float*)d_in[4];
    float* out = (float*)d_out;

    static int grid = 0;
    if (grid == 0) {
        int sm = 0;
        cudaDeviceGetAttribute(&sm, cudaDevAttrMultiProcessorCount, 0);
        if (sm <= 0) sm = 148;
        grid = 2 * sm;
    }

    multig_pool_kernel<<<grid, THREADS>>>(x_sc, x_fc, pool_w, multi_w, multi_b, out);
}

// round 7
// speedup vs baseline: 1.1835x; 1.1835x over previous
#include <cuda_runtime.h>
#include <cstdint>

#define BB 512
#define NN 90
#define DD 1024
#define KK 45
#define THREADS 512
#define WARPS 16

__device__ unsigned g_task_counter;
__device__ unsigned g_done;

__device__ __forceinline__ uint32_t smem_u32(const void* p) {
    uint32_t a;
    asm("{ .reg .u64 t; cvta.to.shared.u64 t, %1; cvt.u32.u64 %0, t; }"
        : "=r"(a) : "l"(p));
    return a;
}
__device__ __forceinline__ float dsmem_ld_f32(uint32_t local_addr, uint32_t peer) {
    uint32_t r; float v;
    asm volatile("mapa.shared::cluster.u32 %0, %1, %2;" : "=r"(r) : "r"(local_addr), "r"(peer));
    asm volatile("ld.shared::cluster.f32 %0, [%1];" : "=f"(v) : "r"(r));
    return v;
}
__device__ __forceinline__ void dsmem_st_u32(uint32_t local_addr, uint32_t peer, unsigned v) {
    uint32_t r;
    asm volatile("mapa.shared::cluster.u32 %0, %1, %2;" : "=r"(r) : "r"(local_addr), "r"(peer));
    asm volatile("st.shared::cluster.u32 [%0], %1;" :: "r"(r), "r"(v) : "memory");
}
__device__ __forceinline__ void cluster_sync() {
    asm volatile("barrier.cluster.arrive.aligned;" ::: "memory");
    asm volatile("barrier.cluster.wait.aligned;" ::: "memory");
}

__global__ __launch_bounds__(THREADS, 2) __cluster_dims__(2, 1, 1)
void multig_pool_kernel(const float* __restrict__ x_sc,
                        const float* __restrict__ x_fc,
                        const float* __restrict__ pool_w,
                        const float* __restrict__ multi_w,
                        const float* __restrict__ multi_b,
                        float* __restrict__ out)
{
    __shared__ __align__(16) float spw[DD];
    __shared__ float s_tanh[NN];     // this CTA's tanh(dot/||w||) for its tensor
    __shared__ float s_scores[NN];
    __shared__ int   sel_idx[KK];
    __shared__ float sel_w[KK];
    __shared__ float red[WARPS];
    __shared__ float s_invnorm;
    __shared__ unsigned s_task;

    const int tid  = threadIdx.x;
    const int wid  = tid >> 5;
    const int lane = tid & 31;

    uint32_t rank;
    asm("mov.u32 %0, %%cluster_ctarank;" : "=r"(rank));
    const uint32_t peer = rank ^ 1u;

    // ---- Once: stage pool_w, 1/||pool_w|| ----
    float pw2 = 0.f;
    {
        float v0 = pool_w[tid];
        float v1 = pool_w[tid + THREADS];
        spw[tid]           = v0;
        spw[tid + THREADS] = v1;
        pw2 = v0 * v0 + v1 * v1;
    }
    #pragma unroll
    for (int off = 16; off; off >>= 1) pw2 += __shfl_xor_sync(0xffffffffu, pw2, off);
    if (lane == 0) red[wid] = pw2;
    __syncthreads();
    if (tid == 0) {
        float s = 0.f;
        #pragma unroll
        for (int i = 0; i < WARPS; i++) s += red[i];
        s_invnorm = rsqrtf(s);
    }
    __syncthreads();

    const float inv_norm = s_invnorm;
    const float mw0 = multi_w[0];
    const float mw1 = multi_w[1];
    const float4* __restrict__ pw4 = (const float4*)spw;
    const uint32_t task_addr = smem_u32(&s_task);
    const uint32_t tanh_addr = smem_u32(&s_tanh[0]);

    // This CTA owns ONE tensor (rank0 = sc, rank1 = fc)
    const float* __restrict__ X  = (rank == 0) ? x_sc : x_fc;
    float* __restrict__ OUT_HALF = out + (size_t)rank * BB * KK * DD;

    // ---- Persistent loop: one cluster = one batch ----
    for (;;) {
        // Rank 0 fetches task and PUSHES it to both CTAs' s_task before the
        // barrier; after SYNC A everyone reads only LOCAL smem (exit-safe).
        if (rank == 0 && tid == 0) {
            unsigned t = atomicAdd(&g_task_counter, 1u);
            s_task = t;
            dsmem_st_u32(task_addr, 1u, t);
        }
        // SYNC A: publishes s_task to both CTAs; also guarantees the peer is
        // done reading my s_tanh from the previous iteration.
        cluster_sync();
        const unsigned b = s_task;     // local read only
        if (b >= BB) break;

        const float* __restrict__ xb = X + (size_t)b * NN * DD;

        // ===== Score all 90 rows of my tensor; 2 nodes/warp for MLP =====
        #pragma unroll
        for (int base = 0; base < NN; base += 2 * WARPS) {   // 0, 32, 64
            const int na = base + wid;                        // always < 90
            const int nb = base + WARPS + wid;                // may be >= 90
            const bool hb = (nb < NN);                        // warp-uniform
            const float4* ra = (const float4*)(xb + (size_t)na * DD);
            const float4* rb = (const float4*)(xb + (size_t)(hb ? nb : na) * DD);
            float da = 0.f, db = 0.f;
            #pragma unroll
            for (int i = 0; i < 8; i++) {
                int j = lane + i * 32;
                float4 a = ra[j];
                float4 c = rb[j];
                float4 p = pw4[j];
                da += a.x * p.x + a.y * p.y + a.z * p.z + a.w * p.w;
                db += c.x * p.x + c.y * p.y + c.z * p.z + c.w * p.w;
            }
            #pragma unroll
            for (int off = 16; off; off >>= 1) {
                da += __shfl_xor_sync(0xffffffffu, da, off);
                db += __shfl_xor_sync(0xffffffffu, db, off);
            }
            if (lane == 0) {
                s_tanh[na] = tanhf(da * inv_norm);
                if (hb) s_tanh[nb] = tanhf(db * inv_norm);
            }
        }
        __syncthreads();

        // SYNC B: my s_tanh visible to peer, peer's visible to me.
        cluster_sync();

        // ===== Combine scores (peer exchange via DSMEM), select top-45 =====
        if (tid < NN) {
            float t_own  = s_tanh[tid];
            float t_peer = dsmem_ld_f32(tanh_addr + 4u * tid, peer);
            float t_sc = (rank == 0) ? t_own  : t_peer;
            float t_fc = (rank == 0) ? t_peer : t_own;
            float z = t_sc * mw0 + t_fc * mw1 + multi_b[tid];
            s_scores[tid] = 1.f / (1.f + expf(-z));
        }
        __syncthreads();
        if (tid < NN) {
            float my = s_scores[tid];
            int r = 0;
            #pragma unroll 10
            for (int j = 0; j < NN; j++) {
                float sj = s_scores[j];
                r += (sj > my) || (sj == my && j < tid);
            }
            if (r < KK) { sel_idx[r] = tid; sel_w[r] = my; }
        }
        __syncthreads();

        // ===== Gather my tensor's 45 selected rows (L2-hot: read <10us ago) =====
        float* __restrict__ ob = OUT_HALF + (size_t)b * KK * DD;
        for (int k = wid; k < KK; k += WARPS) {
            const int   n = sel_idx[k];
            const float w = sel_w[k];
            const float4* src = (const float4*)(xb + (size_t)n * DD);
            float4* dst = (float4*)(ob + (size_t)k * DD);
            #pragma unroll
            for (int i = 0; i < 8; i++) {
                int j = lane + i * 32;
                float4 v = src[j];
                v.x *= w; v.y *= w; v.z *= w; v.w *= w;
                dst[j] = v;
            }
        }
        __syncthreads();   // all threads done with sel/s_scores before reuse
    }

    // Exit barrier: neither CTA leaves while its peer could still touch
    // cluster-shared state (peer s_task pushes target this CTA's smem).
    cluster_sync();

    // ---- Last CTA resets device state for next graph replay ----
    if (tid == 0) {
        unsigned d = atomicAdd(&g_done, 1u) + 1u;
        if (d == gridDim.x) {
            g_task_counter = 0;
            g_done = 0;
        }
    }
}

extern "C" void kernel_launch(void* const* d_in, const int* in_sizes, int n_in,
                              void* d_out, int out_size)
{
    const float* x_sc    = (const float*)d_in[0];
    const float* x_fc    = (const float*)d_in[1];
    const float* pool_w  = (const float*)d_in[2];
    const float* multi_w = (const float*)d_in[3];
    const float* multi_b = (const float*)d_in[4];
    float* out = (float*)d_out;

    static int grid = 0;
    if (grid == 0) {
        int sm = 0;
        cudaDeviceGetAttribute(&sm, cudaDevAttrMultiProcessorCount, 0);
        if (sm <= 0) sm = 148;
        grid = 2 * sm;   // even -> whole clusters; all co-resident
    }

    multig_pool_kernel<<<grid, THREADS>>>(x_sc, x_fc, pool_w, multi_w, multi_b, out);
}